// round 6
// baseline (speedup 1.0000x reference)
#include <cuda_runtime.h>
#include <cuda_bf16.h>
#include <math.h>

// EMLTree1DLinear — strict XLA-style complex64 op graph, PLANAR output.
//
// Diagnosis: four rounds with radically different numerics (fast-fp32, fp64,
// strict-rn fp32) produced rel_err = 0.70743 with <1e-6 variation -> the
// computation is stable and the ~1/sqrt(2) error is a deterministic layout
// transform. All rounds wrote interleaved float2; the harness evidently
// compares against a planar representation (np.stack([re, im]) axis=0).
// This round writes planar: out[0:batch] = real, out[batch:2*batch] = imag,
// selected via out_size (2*batch -> planar; batch -> real-only).
//
// Math kept bit-faithful to XLA:GPU complex64 lowering:
//   cabs(z)  = select(min==0, max, max*sqrt.rn(1+(min/max)^2))
//   clog(z)  = ( logf(cabs), atan2f(im, re) )
//   cmul     = naive, no FMA contraction (__f*_rn)
//   cexp(z)  = expf(re)*(cosf(im), sinf(im))
//   sanitize = nan->0, clamp +-1e6

#define N_LEAVES   1024
#define N_INTERNAL 1023
#define CLAMP_F    1000000.0f

struct C2 { float re, im; };

__device__ __forceinline__ float san1(float v) {
    return (v != v) ? 0.0f : fminf(fmaxf(v, -CLAMP_F), CLAMP_F);
}

__device__ __forceinline__ float xla_cabs(float re, float im) {
    float ar = fabsf(re), ai = fabsf(im);
    float mx = fmaxf(ar, ai);
    float mn = fminf(ar, ai);
    float dv = __fdiv_rn(mn, mx);
    float r  = __fmul_rn(mx, __fsqrt_rn(__fadd_rn(1.0f, __fmul_rn(dv, dv))));
    return (mn == 0.0f) ? mx : r;
}

__device__ __forceinline__ C2 xla_clog(C2 z) {
    C2 r;
    r.re = logf(xla_cabs(z.re, z.im));
    r.im = atan2f(z.im, z.re);
    return r;
}

__device__ __forceinline__ C2 xla_cmul(C2 a, C2 b) {
    C2 r;
    r.re = __fsub_rn(__fmul_rn(a.re, b.re), __fmul_rn(a.im, b.im));
    r.im = __fadd_rn(__fmul_rn(a.re, b.im), __fmul_rn(a.im, b.re));
    return r;
}

__device__ __forceinline__ C2 xla_cexp(C2 z) {
    float e = expf(z.re);
    C2 r;
    r.re = __fmul_rn(e, cosf(z.im));
    r.im = __fmul_rn(e, sinf(z.im));
    return r;
}

__device__ __forceinline__ C2 eml_merge(C2 u, C2 v) {
    C2 w = xla_cexp(xla_cmul(xla_clog(u), xla_clog(v)));
    w.re = san1(w.re);
    w.im = san1(w.im);
    return w;
}

// (g0+0i) + (g1+0i)*(x+0i) + (g2+0i)*val — full naive expansion, signed zeros
// flow to atan2 exactly as in the reference.
__device__ __forceinline__ C2 eml_affine(float g0, float g1, float g2,
                                         float xv, C2 val) {
    float t1r = __fsub_rn(__fmul_rn(g1, xv),   __fmul_rn(0.0f, 0.0f));
    float t1i = __fadd_rn(__fmul_rn(g1, 0.0f), __fmul_rn(0.0f, xv));
    float t2r = __fadd_rn(g0, t1r);
    float t2i = __fadd_rn(0.0f, t1i);
    float t3r = __fsub_rn(__fmul_rn(g2, val.re), __fmul_rn(0.0f, val.im));
    float t3i = __fadd_rn(__fmul_rn(g2, val.im), __fmul_rn(0.0f, val.re));
    C2 r;
    r.re = __fadd_rn(t2r, t3r);
    r.im = __fadd_rn(t2i, t3i);
    return r;
}

__global__ void __launch_bounds__(128)
eml_tree_kernel(const float* __restrict__ x,
                const float* __restrict__ leaf,   // [1024][2]
                const float* __restrict__ gate,   // [1023][2][3]
                float* __restrict__ out,
                int batch, int write_imag) {
    __shared__ float s_leaf[N_LEAVES * 2];
    __shared__ float s_gate[N_INTERNAL * 6];

    for (int i = threadIdx.x; i < N_LEAVES * 2; i += blockDim.x)
        s_leaf[i] = leaf[i];
    for (int i = threadIdx.x; i < N_INTERNAL * 6; i += blockDim.x)
        s_gate[i] = gate[i];
    __syncthreads();

    int gid = blockIdx.x * blockDim.x + threadIdx.x;
    if (gid >= batch) return;

    const float xv = x[gid];

    C2 pend[11];                   // pend[h] = left-sibling value at height h
    C2 v; v.re = 0.0f; v.im = 0.0f;

    #pragma unroll 1
    for (int p = 0; p < 512; ++p) {
        // leaves 2p, 2p+1: (a+0i) + (b+0i)*(x+0i)
        C2 lf0, lf1;
        {
            float a0 = s_leaf[4 * p + 0], b0 = s_leaf[4 * p + 1];
            float r0 = __fsub_rn(__fmul_rn(b0, xv),   __fmul_rn(0.0f, 0.0f));
            float i0 = __fadd_rn(__fmul_rn(b0, 0.0f), __fmul_rn(0.0f, xv));
            lf0.re = __fadd_rn(a0, r0);
            lf0.im = __fadd_rn(0.0f, i0);
            float a1 = s_leaf[4 * p + 2], b1 = s_leaf[4 * p + 3];
            float r1 = __fsub_rn(__fmul_rn(b1, xv),   __fmul_rn(0.0f, 0.0f));
            float i1 = __fadd_rn(__fmul_rn(b1, 0.0f), __fmul_rn(0.0f, xv));
            lf1.re = __fadd_rn(a1, r1);
            lf1.im = __fadd_rn(0.0f, i1);
        }

        // level-0 merge with gate p
        const float* g0 = &s_gate[6 * p];
        C2 li = eml_affine(g0[0], g0[1], g0[2], xv, lf0);
        C2 ri = eml_affine(g0[3], g0[4], g0[5], xv, lf1);
        v = eml_merge(li, ri);

        // pending merges: one per trailing zero of (p+1)
        int nmerge = __ffs(p + 1) - 1;
        int h = 1;
        #pragma unroll 1
        for (int j = 0; j < nmerge; ++j, ++h) {
            C2 lft = pend[h];
            int gidx = N_LEAVES - (N_LEAVES >> h) + (p >> h);
            const float* gg = &s_gate[6 * gidx];
            C2 a = eml_affine(gg[0], gg[1], gg[2], xv, lft);
            C2 b = eml_affine(gg[3], gg[4], gg[5], xv, v);
            v = eml_merge(a, b);
        }
        pend[h] = v;
    }

    // PLANAR output: reals first, imags second half.
    out[gid] = v.re;
    if (write_imag)
        out[batch + gid] = v.im;
}

extern "C" void kernel_launch(void* const* d_in, const int* in_sizes, int n_in,
                              void* d_out, int out_size) {
    // Map inputs by unique element counts: x=65536, leaf=2048, gate=6138
    const float* x = nullptr;
    const float* leaf = nullptr;
    const float* gate = nullptr;
    int batch = 0;
    for (int i = 0; i < n_in; ++i) {
        if (in_sizes[i] == N_LEAVES * 2)        leaf = (const float*)d_in[i];
        else if (in_sizes[i] == N_INTERNAL * 6) gate = (const float*)d_in[i];
        else { x = (const float*)d_in[i]; batch = in_sizes[i]; }
    }

    // out_size == 2*batch float32 -> planar (re block, im block)
    // out_size == batch           -> real part only (interleaved complex64
    //                                at this size is falsified by R1-R5)
    int write_imag = (out_size >= 2 * batch) ? 1 : 0;

    int threads = 128;
    int blocks = (batch + threads - 1) / threads;
    eml_tree_kernel<<<blocks, threads>>>(x, leaf, gate, (float*)d_out,
                                         batch, write_imag);
}

// round 7
// speedup vs baseline: 3.9639x; 3.9639x over previous
#include <cuda_runtime.h>
#include <cuda_bf16.h>
#include <math.h>

// EMLTree1DLinear — planar output (PROVEN R6), fast-intrinsic transcendentals.
// Structure identical to the R6 passing kernel; libdevice logf/atan2f/expf/
// sincosf replaced by a fused MUFU-based clog (shared divide, minimax atan)
// and __expf/__sincosf. Affine/cmul/sanitize remain strict __f*_rn with full
// signed-zero propagation (branch cuts at atan2 depend on them).
// Contraction evidence (R1 fast-fp32 vs R2 fp64 outputs agreed ~1e-6) bounds
// the accumulated fast-math drift well under the 1e-3 threshold.

#define N_LEAVES   1024
#define N_INTERNAL 1023
#define CLAMP_F    1000000.0f
#define PI_F       3.14159265358979323846f
#define PI_2_F     1.57079632679489661923f

struct C2 { float re, im; };

__device__ __forceinline__ float san1(float v) {
    return (v != v) ? 0.0f : fminf(fmaxf(v, -CLAMP_F), CLAMP_F);
}

// Fused complex log: Lr = log|z| (scaled hypot), Li = atan2(im, re).
// One divide shared between both. Signed-zero / branch-cut exact:
//   atan2(+-0, pos) = +-0 ; atan2(+-0, neg or -0) = +-pi ; atan2(y, +-0) = +-pi/2
__device__ __forceinline__ C2 fast_clog(C2 z) {
    float ax = fabsf(z.re), ay = fabsf(z.im);
    float mx = fmaxf(ax, ay);
    float mn = fminf(ax, ay);
    float t  = (mx == 0.0f) ? 0.0f : __fdividef(mn, mx);
    float t2 = t * t;

    // log|z| = log(mx) + 0.5*log(1 + t^2)
    float Lr = __logf(mx) + 0.5f * __logf(1.0f + t2);

    // atan(t) on [0,1], degree-11 odd minimax (~1e-7 abs err)
    float p = t * (0.99997726f + t2 * (-0.33262347f + t2 * (0.19354346f +
              t2 * (-0.11643287f + t2 * (0.05265332f + t2 * (-0.01172120f))))));
    float r = (ay > ax) ? (PI_2_F - p) : p;
    if (__float_as_uint(z.re) & 0x80000000u)   // re negative or -0
        r = PI_F - r;
    C2 o;
    o.re = Lr;
    o.im = copysignf(r, z.im);
    return o;
}

// exp( clog(u)*clog(v) ), sanitized. cmul strict _rn (signed-zero exact:
// mi = Ar*(+-0) + (+-0)*Br yields -0 iff both logs negative -> sin(-0) = -0).
__device__ __forceinline__ C2 eml_merge(C2 u, C2 v) {
    C2 A = fast_clog(u);
    C2 B = fast_clog(v);
    float mr = __fsub_rn(__fmul_rn(A.re, B.re), __fmul_rn(A.im, B.im));
    float mi = __fadd_rn(__fmul_rn(A.re, B.im), __fmul_rn(A.im, B.re));
    float e = __expf(mr);
    float s, c;
    __sincosf(mi, &s, &c);
    C2 w;
    w.re = san1(__fmul_rn(e, c));
    w.im = san1(__fmul_rn(e, s));
    return w;
}

// (g0+0i) + (g1+0i)*(x+0i) + (g2+0i)*val — full naive expansion, strict _rn,
// signed zeros reach atan2 exactly as in the reference. (proven R6)
__device__ __forceinline__ C2 eml_affine(float g0, float g1, float g2,
                                         float xv, C2 val) {
    float t1r = __fsub_rn(__fmul_rn(g1, xv),   __fmul_rn(0.0f, 0.0f));
    float t1i = __fadd_rn(__fmul_rn(g1, 0.0f), __fmul_rn(0.0f, xv));
    float t2r = __fadd_rn(g0, t1r);
    float t2i = __fadd_rn(0.0f, t1i);
    float t3r = __fsub_rn(__fmul_rn(g2, val.re), __fmul_rn(0.0f, val.im));
    float t3i = __fadd_rn(__fmul_rn(g2, val.im), __fmul_rn(0.0f, val.re));
    C2 r;
    r.re = __fadd_rn(t2r, t3r);
    r.im = __fadd_rn(t2i, t3i);
    return r;
}

__global__ void __launch_bounds__(128)
eml_tree_kernel(const float* __restrict__ x,
                const float* __restrict__ leaf,   // [1024][2]
                const float* __restrict__ gate,   // [1023][2][3]
                float* __restrict__ out,
                int batch, int write_imag) {
    __shared__ float s_leaf[N_LEAVES * 2];
    __shared__ float s_gate[N_INTERNAL * 6];

    for (int i = threadIdx.x; i < N_LEAVES * 2; i += blockDim.x)
        s_leaf[i] = leaf[i];
    for (int i = threadIdx.x; i < N_INTERNAL * 6; i += blockDim.x)
        s_gate[i] = gate[i];
    __syncthreads();

    int gid = blockIdx.x * blockDim.x + threadIdx.x;
    if (gid >= batch) return;

    const float xv = x[gid];

    C2 pend[11];                   // pend[h] = left-sibling value at height h
    C2 v; v.re = 0.0f; v.im = 0.0f;

    #pragma unroll 1
    for (int p = 0; p < 512; ++p) {
        // leaves 2p, 2p+1: (a+0i) + (b+0i)*(x+0i), full expansion
        C2 lf0, lf1;
        {
            float a0 = s_leaf[4 * p + 0], b0 = s_leaf[4 * p + 1];
            float r0 = __fsub_rn(__fmul_rn(b0, xv),   __fmul_rn(0.0f, 0.0f));
            float i0 = __fadd_rn(__fmul_rn(b0, 0.0f), __fmul_rn(0.0f, xv));
            lf0.re = __fadd_rn(a0, r0);
            lf0.im = __fadd_rn(0.0f, i0);
            float a1 = s_leaf[4 * p + 2], b1 = s_leaf[4 * p + 3];
            float r1 = __fsub_rn(__fmul_rn(b1, xv),   __fmul_rn(0.0f, 0.0f));
            float i1 = __fadd_rn(__fmul_rn(b1, 0.0f), __fmul_rn(0.0f, xv));
            lf1.re = __fadd_rn(a1, r1);
            lf1.im = __fadd_rn(0.0f, i1);
        }

        // level-0 merge with gate p
        const float* g0 = &s_gate[6 * p];
        C2 li = eml_affine(g0[0], g0[1], g0[2], xv, lf0);
        C2 ri = eml_affine(g0[3], g0[4], g0[5], xv, lf1);
        v = eml_merge(li, ri);

        // pending merges: one per trailing zero of (p+1)
        int nmerge = __ffs(p + 1) - 1;
        int h = 1;
        #pragma unroll 1
        for (int j = 0; j < nmerge; ++j, ++h) {
            C2 lft = pend[h];
            int gidx = N_LEAVES - (N_LEAVES >> h) + (p >> h);
            const float* gg = &s_gate[6 * gidx];
            C2 a = eml_affine(gg[0], gg[1], gg[2], xv, lft);
            C2 b = eml_affine(gg[3], gg[4], gg[5], xv, v);
            v = eml_merge(a, b);
        }
        pend[h] = v;
    }

    // PLANAR output: reals first, imags second half (PROVEN R6).
    out[gid] = v.re;
    if (write_imag)
        out[batch + gid] = v.im;
}

extern "C" void kernel_launch(void* const* d_in, const int* in_sizes, int n_in,
                              void* d_out, int out_size) {
    // Map inputs by unique element counts: x=65536, leaf=2048, gate=6138
    const float* x = nullptr;
    const float* leaf = nullptr;
    const float* gate = nullptr;
    int batch = 0;
    for (int i = 0; i < n_in; ++i) {
        if (in_sizes[i] == N_LEAVES * 2)        leaf = (const float*)d_in[i];
        else if (in_sizes[i] == N_INTERNAL * 6) gate = (const float*)d_in[i];
        else { x = (const float*)d_in[i]; batch = in_sizes[i]; }
    }

    int write_imag = (out_size >= 2 * batch) ? 1 : 0;

    int threads = 128;
    int blocks = (batch + threads - 1) / threads;
    eml_tree_kernel<<<blocks, threads>>>(x, leaf, gate, (float*)d_out,
                                         batch, write_imag);
}

// round 9
// speedup vs baseline: 5.9905x; 1.5113x over previous
#include <cuda_runtime.h>
#include <cuda_bf16.h>
#include <math.h>

// EMLTree1DLinear — planar output (PROVEN), lean DFS with static bottom levels.
// R7 evidence: recurrence is strongly contracting (fast intrinsics moved final
// rel_err only 5.5e-8 -> 6.0e-8), so FMA contraction of the affines is safe.
// Signed-zero semantics preserved exactly:
//   affine im = fmaf(g2, val.im, +0)  == reference's ((0+(g1*0+0*x)) + (g2*im+0*re))
//   (outer +0 launders any -0; nonzero path identical rounding)
//   level-0/1 chain values have im == +0 exactly -> real-specialized clog.
// 64-thread blocks, no smem: params via __ldg (warp-uniform -> L1 broadcast);
// 1024 blocks -> 14-vs-12 warps/SM instead of 16-vs-12 (issue-bound tail).

#define N_LEAVES   1024
#define N_INTERNAL 1023
#define CLAMP_F    1000000.0f
#define PI_F       3.14159265358979323846f
#define PI_2_F     1.57079632679489661923f

struct C2 { float re, im; };

__device__ __forceinline__ float san1(float v) {
    return (v != v) ? 0.0f : fminf(fmaxf(v, -CLAMP_F), CLAMP_F);
}

// sanitize(cexp(A*B)) — strict _rn complex mul keeps signed zeros / inf*0=NaN
__device__ __forceinline__ C2 cexp_mul_san(float Ar, float Ai, float Br, float Bi) {
    float mr = __fsub_rn(__fmul_rn(Ar, Br), __fmul_rn(Ai, Bi));
    float mi = __fadd_rn(__fmul_rn(Ar, Bi), __fmul_rn(Ai, Br));
    float e = __expf(mr);
    float s, c;
    __sincosf(mi, &s, &c);
    C2 w;
    w.re = san1(__fmul_rn(e, c));
    w.im = san1(__fmul_rn(e, s));
    return w;
}

// complex log, branch-cut exact (PROVEN R7): Lr = log|z| scaled-hypot,
// Li = atan2(im, re) via shared divide + deg-11 minimax.
__device__ __forceinline__ C2 fast_clog(C2 z) {
    float ax = fabsf(z.re), ay = fabsf(z.im);
    float mx = fmaxf(ax, ay);
    float mn = fminf(ax, ay);
    float t  = (mx == 0.0f) ? 0.0f : __fdividef(mn, mx);
    float t2 = t * t;
    float Lr = __logf(mx) + 0.5f * __logf(1.0f + t2);
    float p = t * (0.99997726f + t2 * (-0.33262347f + t2 * (0.19354346f +
              t2 * (-0.11643287f + t2 * (0.05265332f + t2 * (-0.01172120f))))));
    float r = (ay > ax) ? (PI_2_F - p) : p;
    if (__float_as_uint(z.re) & 0x80000000u)   // re negative or -0
        r = PI_F - r;
    C2 o;
    o.re = Lr;
    o.im = copysignf(r, z.im);
    return o;
}

__device__ __forceinline__ C2 merge_gen(C2 u, C2 w) {
    C2 A = fast_clog(u);
    C2 B = fast_clog(w);
    return cexp_mul_san(A.re, A.im, B.re, B.im);
}

// merge of two purely-real inputs (im == +0): clog degenerates.
// atan2(+0, re) = +0 (re>=+0) / +pi (re<0 or -0); log|re| incl. log(0)=-inf.
__device__ __forceinline__ C2 merge_real(float lu, float rv) {
    float Ar = __logf(fabsf(lu));
    float Ai = (__float_as_uint(lu) >> 31) ? PI_F : 0.0f;
    float Br = __logf(fabsf(rv));
    float Bi = (__float_as_uint(rv) >> 31) ? PI_F : 0.0f;
    return cexp_mul_san(Ar, Ai, Br, Bi);
}

// (g0 + g1*x) + g2*val — reduced form, signed-zero-exact imag laundering.
__device__ __forceinline__ C2 affine(float g0, float g1, float g2,
                                     float xv, C2 val) {
    C2 r;
    r.re = __fmaf_rn(g2, val.re, __fmaf_rn(g1, xv, g0));
    r.im = __fmaf_rn(g2, val.im, 0.0f);
    return r;
}

__global__ void __launch_bounds__(64)
eml_tree_kernel(const float* __restrict__ x,
                const float* __restrict__ leaf,   // [1024][2]
                const float* __restrict__ gate,   // [1023][2][3]
                float* __restrict__ out,
                int batch, int write_imag) {
    int gid = blockIdx.x * blockDim.x + threadIdx.x;
    if (gid >= batch) return;

    const float xv = __ldg(x + gid);
    const float4* leaf4 = (const float4*)leaf;
    const float4* gate4 = (const float4*)gate;
    const float2* gate2 = (const float2*)gate;

    C2 pend[11];                   // heights 2..10
    C2 v; v.re = 0.0f; v.im = 0.0f;

    #pragma unroll 1
    for (int q = 0; q < 256; ++q) {
        // ---- two level-0 merges (leaf pairs 2q, 2q+1), purely real ----
        float4 LA = __ldg(leaf4 + 2 * q);        // leaves 4q, 4q+1
        float4 LB = __ldg(leaf4 + 2 * q + 1);    // leaves 4q+2, 4q+3
        float4 G0 = __ldg(gate4 + 3 * q);        // gates 2q, 2q+1 (12 floats)
        float4 G1 = __ldg(gate4 + 3 * q + 1);
        float4 G2 = __ldg(gate4 + 3 * q + 2);

        float u0 = __fmaf_rn(LA.y, xv, LA.x);
        float u1 = __fmaf_rn(LA.w, xv, LA.z);
        float lu0 = __fmaf_rn(G0.z, u0, __fmaf_rn(G0.y, xv, G0.x));
        float rv0 = __fmaf_rn(G1.y, u1, __fmaf_rn(G1.x, xv, G0.w));
        C2 v1 = merge_real(lu0, rv0);

        float u2 = __fmaf_rn(LB.y, xv, LB.x);
        float u3 = __fmaf_rn(LB.w, xv, LB.z);
        float lu1 = __fmaf_rn(G2.x, u2, __fmaf_rn(G1.w, xv, G1.z));
        float rv1 = __fmaf_rn(G2.w, u3, __fmaf_rn(G2.z, xv, G2.y));
        C2 v2 = merge_real(lu1, rv1);

        // ---- static level-1 merge: gate node 512+q ----
        const float2* hp = gate2 + 3 * (512 + q);
        float2 H0 = __ldg(hp);
        float2 H1 = __ldg(hp + 1);
        float2 H2 = __ldg(hp + 2);
        C2 A = affine(H0.x, H0.y, H1.x, xv, v1);
        C2 B = affine(H1.y, H2.x, H2.y, xv, v2);
        v = merge_gen(A, B);

        // ---- dynamic merges at heights >= 2: one per trailing zero of q+1 ----
        int n = __ffs(q + 1) - 1;
        int h = 2;
        #pragma unroll 1
        for (int j = 0; j < n; ++j, ++h) {
            C2 lft = pend[h];
            int gidx = N_LEAVES - (N_LEAVES >> h) + (q >> (h - 1));
            const float2* gp = gate2 + 3 * gidx;
            float2 D0 = __ldg(gp);
            float2 D1 = __ldg(gp + 1);
            float2 D2 = __ldg(gp + 2);
            C2 a = affine(D0.x, D0.y, D1.x, xv, lft);
            C2 b = affine(D1.y, D2.x, D2.y, xv, v);
            v = merge_gen(a, b);
        }
        pend[h] = v;
    }

    // PLANAR output: reals first, imags second half (PROVEN).
    out[gid] = v.re;
    if (write_imag)
        out[batch + gid] = v.im;
}

extern "C" void kernel_launch(void* const* d_in, const int* in_sizes, int n_in,
                              void* d_out, int out_size) {
    // Map inputs by unique element counts: x=65536, leaf=2048, gate=6138
    const float* x = nullptr;
    const float* leaf = nullptr;
    const float* gate = nullptr;
    int batch = 0;
    for (int i = 0; i < n_in; ++i) {
        if (in_sizes[i] == N_LEAVES * 2)        leaf = (const float*)d_in[i];
        else if (in_sizes[i] == N_INTERNAL * 6) gate = (const float*)d_in[i];
        else { x = (const float*)d_in[i]; batch = in_sizes[i]; }
    }

    int write_imag = (out_size >= 2 * batch) ? 1 : 0;

    int threads = 64;
    int blocks = (batch + threads - 1) / threads;
    eml_tree_kernel<<<blocks, threads>>>(x, leaf, gate, (float*)d_out,
                                         batch, write_imag);
}

// round 11
// speedup vs baseline: 7.0826x; 1.1823x over previous
#include <cuda_runtime.h>
#include <cuda_bf16.h>
#include <math.h>

// EMLTree1DLinear — planar output (PROVEN), 2-threads-per-element tree split.
// R9 showed latency-bound (issue 61%, occ 21%): one thread/element caps the
// chip at 13.8 warps/SM. Split each 1024-leaf tree into two 512-leaf halves,
// one thread each (height-9 subtree), exchange half-roots via __shfl_xor and
// redundantly compute the height-10 root merge (gate 1022) on both threads.
// Arithmetic is bit-identical to the R9 passing kernel (same ops, same gate
// indices); only the work partition changes. Occ doubles -> latency hidden.

#define N_LEAVES   1024
#define N_INTERNAL 1023
#define CLAMP_F    1000000.0f
#define PI_F       3.14159265358979323846f
#define PI_2_F     1.57079632679489661923f

struct C2 { float re, im; };

__device__ __forceinline__ float san1(float v) {
    return (v != v) ? 0.0f : fminf(fmaxf(v, -CLAMP_F), CLAMP_F);
}

// sanitize(cexp(A*B)) — strict _rn complex mul keeps signed zeros / inf*0=NaN
__device__ __forceinline__ C2 cexp_mul_san(float Ar, float Ai, float Br, float Bi) {
    float mr = __fsub_rn(__fmul_rn(Ar, Br), __fmul_rn(Ai, Bi));
    float mi = __fadd_rn(__fmul_rn(Ar, Bi), __fmul_rn(Ai, Br));
    float e = __expf(mr);
    float s, c;
    __sincosf(mi, &s, &c);
    C2 w;
    w.re = san1(__fmul_rn(e, c));
    w.im = san1(__fmul_rn(e, s));
    return w;
}

// complex log, branch-cut exact (PROVEN): Lr = log|z| scaled-hypot,
// Li = atan2(im, re) via shared divide + deg-11 minimax.
__device__ __forceinline__ C2 fast_clog(C2 z) {
    float ax = fabsf(z.re), ay = fabsf(z.im);
    float mx = fmaxf(ax, ay);
    float mn = fminf(ax, ay);
    float t  = (mx == 0.0f) ? 0.0f : __fdividef(mn, mx);
    float t2 = t * t;
    float Lr = __logf(mx) + 0.5f * __logf(1.0f + t2);
    float p = t * (0.99997726f + t2 * (-0.33262347f + t2 * (0.19354346f +
              t2 * (-0.11643287f + t2 * (0.05265332f + t2 * (-0.01172120f))))));
    float r = (ay > ax) ? (PI_2_F - p) : p;
    if (__float_as_uint(z.re) & 0x80000000u)   // re negative or -0
        r = PI_F - r;
    C2 o;
    o.re = Lr;
    o.im = copysignf(r, z.im);
    return o;
}

__device__ __forceinline__ C2 merge_gen(C2 u, C2 w) {
    C2 A = fast_clog(u);
    C2 B = fast_clog(w);
    return cexp_mul_san(A.re, A.im, B.re, B.im);
}

// merge of two purely-real inputs (im == +0): clog degenerates.
__device__ __forceinline__ C2 merge_real(float lu, float rv) {
    float Ar = __logf(fabsf(lu));
    float Ai = (__float_as_uint(lu) >> 31) ? PI_F : 0.0f;
    float Br = __logf(fabsf(rv));
    float Bi = (__float_as_uint(rv) >> 31) ? PI_F : 0.0f;
    return cexp_mul_san(Ar, Ai, Br, Bi);
}

// (g0 + g1*x) + g2*val — reduced form, signed-zero-exact imag laundering.
__device__ __forceinline__ C2 affine(float g0, float g1, float g2,
                                     float xv, C2 val) {
    C2 r;
    r.re = __fmaf_rn(g2, val.re, __fmaf_rn(g1, xv, g0));
    r.im = __fmaf_rn(g2, val.im, 0.0f);
    return r;
}

__global__ void __launch_bounds__(64)
eml_tree_kernel(const float* __restrict__ x,
                const float* __restrict__ leaf,   // [1024][2]
                const float* __restrict__ gate,   // [1023][2][3]
                float* __restrict__ out,
                int batch, int write_imag) {
    int tid  = blockIdx.x * blockDim.x + threadIdx.x;
    int elem = tid >> 1;          // batch element
    int half = tid & 1;           // 0 = left 512 leaves, 1 = right 512 leaves
    if (elem >= batch) return;

    const float xv = __ldg(x + elem);
    const float4* leaf4 = (const float4*)leaf;
    const float4* gate4 = (const float4*)gate;
    const float2* gate2 = (const float2*)gate;

    const int qbase = half << 7;   // 128 iterations per half

    C2 pend[10];                   // loop-heights 2..9
    C2 v; v.re = 0.0f; v.im = 0.0f;

    #pragma unroll 1
    for (int ql = 0; ql < 128; ++ql) {
        int q = qbase + ql;        // global quad index (same as R9's q)

        // ---- two level-0 merges (leaf pairs 2q, 2q+1), purely real ----
        float4 LA = __ldg(leaf4 + 2 * q);
        float4 LB = __ldg(leaf4 + 2 * q + 1);
        float4 G0 = __ldg(gate4 + 3 * q);
        float4 G1 = __ldg(gate4 + 3 * q + 1);
        float4 G2 = __ldg(gate4 + 3 * q + 2);

        float u0 = __fmaf_rn(LA.y, xv, LA.x);
        float u1 = __fmaf_rn(LA.w, xv, LA.z);
        float lu0 = __fmaf_rn(G0.z, u0, __fmaf_rn(G0.y, xv, G0.x));
        float rv0 = __fmaf_rn(G1.y, u1, __fmaf_rn(G1.x, xv, G0.w));
        C2 v1 = merge_real(lu0, rv0);

        float u2 = __fmaf_rn(LB.y, xv, LB.x);
        float u3 = __fmaf_rn(LB.w, xv, LB.z);
        float lu1 = __fmaf_rn(G2.x, u2, __fmaf_rn(G1.w, xv, G1.z));
        float rv1 = __fmaf_rn(G2.w, u3, __fmaf_rn(G2.z, xv, G2.y));
        C2 v2 = merge_real(lu1, rv1);

        // ---- static height-2 merge: gate node 512+q ----
        const float2* hp = gate2 + 3 * (512 + q);
        float2 H0 = __ldg(hp);
        float2 H1 = __ldg(hp + 1);
        float2 H2 = __ldg(hp + 2);
        C2 A = affine(H0.x, H0.y, H1.x, xv, v1);
        C2 B = affine(H1.y, H2.x, H2.y, xv, v2);
        v = merge_gen(A, B);

        // ---- dynamic merges: one per trailing zero of (ql+1), own subtree ----
        int n = __ffs(ql + 1) - 1;
        int h = 2;
        #pragma unroll 1
        for (int j = 0; j < n; ++j, ++h) {
            C2 lft = pend[h];
            int gidx = N_LEAVES - (N_LEAVES >> h) + (q >> (h - 1));
            const float2* gp = gate2 + 3 * gidx;
            float2 D0 = __ldg(gp);
            float2 D1 = __ldg(gp + 1);
            float2 D2 = __ldg(gp + 2);
            C2 a = affine(D0.x, D0.y, D1.x, xv, lft);
            C2 b = affine(D1.y, D2.x, D2.y, xv, v);
            v = merge_gen(a, b);
        }
        pend[h] = v;               // last iter: pend[9] = height-9 half-root
    }

    // ---- cross-thread root merge (gate 1022), computed by both threads ----
    float pr = __shfl_xor_sync(0xffffffffu, v.re, 1);
    float pi = __shfl_xor_sync(0xffffffffu, v.im, 1);
    C2 lft, rgt;
    if (half == 0) { lft = v;                 rgt.re = pr; rgt.im = pi; }
    else           { lft.re = pr; lft.im = pi; rgt = v; }

    const float2* rp = gate2 + 3 * 1022;
    float2 R0 = __ldg(rp);
    float2 R1 = __ldg(rp + 1);
    float2 R2 = __ldg(rp + 2);
    C2 a = affine(R0.x, R0.y, R1.x, xv, lft);
    C2 b = affine(R1.y, R2.x, R2.y, xv, rgt);
    v = merge_gen(a, b);

    // PLANAR output (PROVEN): even lane writes.
    if (half == 0) {
        out[elem] = v.re;
        if (write_imag)
            out[batch + elem] = v.im;
    }
}

extern "C" void kernel_launch(void* const* d_in, const int* in_sizes, int n_in,
                              void* d_out, int out_size) {
    // Map inputs by unique element counts: x=65536, leaf=2048, gate=6138
    const float* x = nullptr;
    const float* leaf = nullptr;
    const float* gate = nullptr;
    int batch = 0;
    for (int i = 0; i < n_in; ++i) {
        if (in_sizes[i] == N_LEAVES * 2)        leaf = (const float*)d_in[i];
        else if (in_sizes[i] == N_INTERNAL * 6) gate = (const float*)d_in[i];
        else { x = (const float*)d_in[i]; batch = in_sizes[i]; }
    }

    int write_imag = (out_size >= 2 * batch) ? 1 : 0;

    int threads = 64;
    long total = 2L * batch;                       // 2 threads per element
    int blocks = (int)((total + threads - 1) / threads);
    eml_tree_kernel<<<blocks, threads>>>(x, leaf, gate, (float*)d_out,
                                         batch, write_imag);
}